// round 8
// baseline (speedup 1.0000x reference)
#include <cuda_runtime.h>
#include <cuda_fp16.h>
#include <cstdint>

// ---------------- problem constants ----------------
#define B_   512
#define N_   100000
#define NPAD 100096    // N padded to multiple of 128
#define D_   256
#define F_   256
#define HA_  128

#define BM 128

#define NT_SIM (NPAD / 128)                // 782 column tiles
#define KC2    1024                        // pred split-K chunk
#define SPL2   ((NPAD + KC2 - 1) / KC2)    // 98 splits

// mma staging geometry
#define KCH   64                           // K halves per stage (128B rows)
#define TILEB 16384                        // 128 rows * 64 halves * 2B
#define STAGEB (4 * TILEB)                 // 4 tiles per stage
#define DYNSM (1024 + 2 * STAGEB)          // align pad + 2 stages

// ---------------- device scratch ----------------
__device__ __align__(16) __half g_zt_hi[(size_t)NPAD * F_];
__device__ __align__(16) __half g_zt_lo[(size_t)NPAD * F_];
__device__ __align__(16) __half g_zq_hi[(size_t)B_ * F_];
__device__ __align__(16) __half g_zq_lo[(size_t)B_ * F_];
__device__ __align__(16) __half g_wt_hi[(size_t)F_ * D_];   // W^T split
__device__ __align__(16) __half g_wt_lo[(size_t)F_ * D_];
__device__ __align__(16) __half g_aT_hi[(size_t)HA_ * NPAD];// actions^T split
__device__ __align__(16) __half g_aT_lo[(size_t)HA_ * NPAD];
__device__ float  g_pmax[(size_t)B_ * NT_SIM];   // per (row, tile) max
__device__ float  g_ptsum[(size_t)B_ * NT_SIM];  // per (row, tile) exp-sum (tile-shifted)
__device__ float  g_rmax[B_];
__device__ float  g_rinv[B_];
__device__ float  g_invT[1];
__device__ float  g_ppred[(size_t)SPL2 * B_ * HA_];

// ---------------- helpers ----------------
__device__ __forceinline__ unsigned su(const void* p) {
    return (unsigned)__cvta_generic_to_shared(p);
}
__device__ __forceinline__ void cp16(unsigned d, const void* s) {
    asm volatile("cp.async.cg.shared.global [%0], [%1], 16;" :: "r"(d), "l"(s));
}
__device__ __forceinline__ void cpcommit() { asm volatile("cp.async.commit_group;"); }
__device__ __forceinline__ void cpwait0()  { asm volatile("cp.async.wait_group 0;"); }
__device__ __forceinline__ void cpwait1()  { asm volatile("cp.async.wait_group 1;"); }

#define LDSM4(r, addr) \
    asm volatile("ldmatrix.sync.aligned.m8n8.x4.shared.b16 {%0,%1,%2,%3}, [%4];" \
        : "=r"((r)[0]), "=r"((r)[1]), "=r"((r)[2]), "=r"((r)[3]) : "r"(addr))
#define LDSM2(r, addr) \
    asm volatile("ldmatrix.sync.aligned.m8n8.x2.shared.b16 {%0,%1}, [%2];" \
        : "=r"((r)[0]), "=r"((r)[1]) : "r"(addr))
#define MMA16816(d, a, b) \
    asm volatile("mma.sync.aligned.m16n8k16.row.col.f32.f16.f16.f32 " \
        "{%0,%1,%2,%3}, {%4,%5,%6,%7}, {%8,%9}, {%0,%1,%2,%3};" \
        : "+f"((d)[0]), "+f"((d)[1]), "+f"((d)[2]), "+f"((d)[3]) \
        : "r"((a)[0]), "r"((a)[1]), "r"((a)[2]), "r"((a)[3]), "r"((b)[0]), "r"((b)[1]))

__device__ __forceinline__ unsigned fkey(float f) {
    unsigned u = __float_as_uint(f);
    return (u & 0x80000000u) ? ~u : (u | 0x80000000u);
}
__device__ __forceinline__ float funkey(unsigned k) {
    return __uint_as_float((k & 0x80000000u) ? (k & 0x7FFFFFFFu) : ~k);
}
__device__ __forceinline__ uint32_t pkh(__half a, __half b) {
    __half2 h = __halves2half2(a, b);
    return *(uint32_t*)&h;
}

__device__ __forceinline__ float fexp(float x)
{
    x = fmaxf(x, -87.0f);
    float t = x * 1.4426950408889634f;
    float n = rintf(t);
    float f = t - n;
    float p =            1.5403530393e-4f;
    p = fmaf(p, f, 1.3333558146e-3f);
    p = fmaf(p, f, 9.6181291076e-3f);
    p = fmaf(p, f, 5.5504108664e-2f);
    p = fmaf(p, f, 2.4022650696e-1f);
    p = fmaf(p, f, 6.9314718056e-1f);
    p = fmaf(p, f, 1.0f);
    int ni = (int)n;
    float s = __int_as_float((ni + 127) << 23);
    return p * s;
}

// ================= kernel: prep (invT) =================
__global__ void prep_kernel(const float* __restrict__ logT)
{
    g_invT[0] = expf(-logT[0]);
}

// ================= kernel: W_enc transpose + fp16 split =================
__global__ void wsplit_kernel(const float* __restrict__ W)
{
    __shared__ float s[32][33];
    const int k0 = blockIdx.x * 32, f0 = blockIdx.y * 32;
    const int tx = threadIdx.x, ty = threadIdx.y;
#pragma unroll
    for (int l = 0; l < 4; l++)
        s[ty + l * 8][tx] = W[(size_t)(k0 + ty + l * 8) * F_ + f0 + tx];
    __syncthreads();
#pragma unroll
    for (int l = 0; l < 4; l++) {
        float v = s[tx][ty + l * 8];
        __half h = __float2half_rn(v);
        __half lo = __float2half_rn(v - __half2float(h));
        g_wt_hi[(size_t)(f0 + ty + l * 8) * D_ + k0 + tx] = h;
        g_wt_lo[(size_t)(f0 + ty + l * 8) * D_ + k0 + tx] = lo;
    }
}

// ================= kernel: actions transpose + fp16 split =================
__global__ void atsplit_kernel(const float* __restrict__ Act)
{
    __shared__ float s[32][33];
    const int n0 = blockIdx.x * 32, j0 = blockIdx.y * 32;
    const int tx = threadIdx.x, ty = threadIdx.y;
#pragma unroll
    for (int l = 0; l < 4; l++) {
        int n = n0 + ty + l * 8;
        float v = 0.f;
        if (n < N_) v = Act[(size_t)n * HA_ + j0 + tx];
        s[ty + l * 8][tx] = v;
    }
    __syncthreads();
#pragma unroll
    for (int l = 0; l < 4; l++) {
        int j = j0 + ty + l * 8;
        float v = s[tx][ty + l * 8];
        __half h = __float2half_rn(v);
        __half lo = __float2half_rn(v - __half2float(h));
        g_aT_hi[(size_t)j * NPAD + n0 + tx] = h;
        g_aT_lo[(size_t)j * NPAD + n0 + tx] = lo;
    }
}

// ================= kernel: encode via mma.sync (fp16-split, 3 products) =================
__global__ __launch_bounds__(256, 1)
void encode_kernel(const float* __restrict__ A,
                   __half* __restrict__ Zh, __half* __restrict__ Zl, int M)
{
    extern __shared__ __align__(16) char dsm_raw[];
    char* dynPtr = (char*)(((uintptr_t)dsm_raw + 1023) & ~(uintptr_t)1023);
    const uint32_t dynBase = su(dynPtr);
    const int tid = threadIdx.x, wid = tid >> 5, t = tid & 31;
    const int warpM = wid >> 2, warpN = wid & 3;
    const int rowBase = blockIdx.y * BM;
    const int colBase = blockIdx.x * 128;

    float4 pa[8];
    auto ldA = [&](int k0) {
#pragma unroll
        for (int i = 0; i < 8; i++) {
            int lin = tid + i * 256;
            int row = lin >> 4;
            int c4 = (lin & 15) << 2;
            int gr = rowBase + row;
            pa[i] = make_float4(0.f, 0.f, 0.f, 0.f);
            if (gr < M) pa[i] = *(const float4*)(A + (size_t)gr * D_ + k0 + c4);
        }
    };
    auto stsA = [&](int st) {
        char* sb = dynPtr + st * STAGEB;
#pragma unroll
        for (int i = 0; i < 8; i++) {
            int lin = tid + i * 256;
            int row = lin >> 4;
            int c4 = (lin & 15) << 2;
            uint32_t off = (uint32_t)(row * 128 + c4 * 2) ^ (uint32_t)((row & 7) * 16);
            float v[4] = {pa[i].x, pa[i].y, pa[i].z, pa[i].w};
            __half h[4], l[4];
#pragma unroll
            for (int j = 0; j < 4; j++) {
                h[j] = __float2half_rn(v[j]);
                l[j] = __float2half_rn(v[j] - __half2float(h[j]));
            }
            uint2 uh = make_uint2(pkh(h[0], h[1]), pkh(h[2], h[3]));
            uint2 ul = make_uint2(pkh(l[0], l[1]), pkh(l[2], l[3]));
            *(uint2*)(sb + off) = uh;
            *(uint2*)(sb + TILEB + off) = ul;
        }
    };
    auto cpB = [&](int st, int k0) {
        const uint32_t sb = dynBase + st * STAGEB;
#pragma unroll
        for (int i = 0; i < 4; i++) {
            int lin = tid + i * 256;
            int row = lin >> 3, c16 = lin & 7;
            uint32_t off = (uint32_t)(row * 128 + c16 * 16) ^ (uint32_t)((row & 7) * 16);
            cp16(sb + 2 * TILEB + off, g_wt_hi + (size_t)(colBase + row) * D_ + k0 + c16 * 8);
            cp16(sb + 3 * TILEB + off, g_wt_lo + (size_t)(colBase + row) * D_ + k0 + c16 * 8);
        }
        cpcommit();
    };

    const uint32_t xorv = (uint32_t)((t & 7) * 16);
    uint32_t aOff[4], bOff[4];
#pragma unroll
    for (int mt = 0; mt < 4; mt++) {
        int row = warpM * 64 + mt * 16 + (t & 15);
        aOff[mt] = (uint32_t)(row * 128 + (t >> 4) * 16);
    }
#pragma unroll
    for (int nt = 0; nt < 4; nt++) {
        int row = warpN * 32 + nt * 8 + (t & 7);
        bOff[nt] = (uint32_t)(row * 128 + ((t >> 3) & 1) * 16);
    }

    float acc[4][4][4];
#pragma unroll
    for (int mt = 0; mt < 4; mt++)
#pragma unroll
        for (int nt = 0; nt < 4; nt++)
#pragma unroll
            for (int j = 0; j < 4; j++) acc[mt][nt][j] = 0.f;

    ldA(0); cpB(0, 0);
    stsA(0); cpwait0(); __syncthreads();

    for (int it = 0; it < 4; it++) {
        const int cur = it & 1;
        if (it < 3) { ldA((it + 1) * KCH); cpB(cur ^ 1, (it + 1) * KCH); }
        const uint32_t sb = dynBase + cur * STAGEB;
#pragma unroll
        for (int k16 = 0; k16 < 4; k16++) {
            uint32_t ah[4][4], al[4][4], bh[4][2], bl[4][2];
#pragma unroll
            for (int mt = 0; mt < 4; mt++) {
                uint32_t o = (aOff[mt] + k16 * 32) ^ xorv;
                LDSM4(ah[mt], sb + o);
                LDSM4(al[mt], sb + TILEB + o);
            }
#pragma unroll
            for (int nt = 0; nt < 4; nt++) {
                uint32_t o = (bOff[nt] + k16 * 32) ^ xorv;
                LDSM2(bh[nt], sb + 2 * TILEB + o);
                LDSM2(bl[nt], sb + 3 * TILEB + o);
            }
#pragma unroll
            for (int mt = 0; mt < 4; mt++)
#pragma unroll
                for (int nt = 0; nt < 4; nt++) {
                    MMA16816(acc[mt][nt], ah[mt], bh[nt]);
                    MMA16816(acc[mt][nt], ah[mt], bl[nt]);
                    MMA16816(acc[mt][nt], al[mt], bh[nt]);
                }
        }
        if (it < 3) { stsA(cur ^ 1); cpwait0(); }
        __syncthreads();
    }

    const int qr = t >> 2, qc = (t & 3) * 2;
#pragma unroll
    for (int mt = 0; mt < 4; mt++)
#pragma unroll
        for (int h = 0; h < 2; h++) {
            const size_t m = (size_t)(rowBase + warpM * 64 + mt * 16 + qr + h * 8);
#pragma unroll
            for (int nt = 0; nt < 4; nt++) {
                const int gc = colBase + warpN * 32 + nt * 8 + qc;
                float x = acc[mt][nt][h * 2 + 0];
                float y = acc[mt][nt][h * 2 + 1];
                __half hx = __float2half_rn(x), hy = __float2half_rn(y);
                __half lx = __float2half_rn(x - __half2float(hx));
                __half ly = __float2half_rn(y - __half2float(hy));
                *(__half2*)(Zh + m * F_ + gc) = __halves2half2(hx, hy);
                *(__half2*)(Zl + m * F_ + gc) = __halves2half2(lx, ly);
            }
        }
}

// ================= kernel: sim via mma.sync + per-tile (max, exp-sum) =================
__global__ __launch_bounds__(256, 1)
void sim_kernel(const long long* __restrict__ qidx, float* __restrict__ Wout)
{
    extern __shared__ __align__(16) char dsm_raw[];
    __shared__ int      s_q[BM];
    __shared__ unsigned s_red[BM];
    __shared__ float    s_red2[BM][4];

    char* dynPtr = (char*)(((uintptr_t)dsm_raw + 1023) & ~(uintptr_t)1023);
    const uint32_t dynBase = su(dynPtr);
    const int tid = threadIdx.x, wid = tid >> 5, t = tid & 31;
    const int warpM = wid >> 2, warpN = wid & 3;
    const int rowBase = blockIdx.y * BM;
    const int colBase = blockIdx.x * 128;

    if (tid < BM) { s_q[tid] = (int)qidx[rowBase + tid]; s_red[tid] = 0u; }

    const __half* srcs[4] = { g_zq_hi + (size_t)rowBase * F_, g_zq_lo + (size_t)rowBase * F_,
                              g_zt_hi + (size_t)colBase * F_, g_zt_lo + (size_t)colBase * F_ };
    auto loadStage = [&](int st, int ck) {
        const int k0 = ck * KCH;
        const uint32_t sb = dynBase + st * STAGEB;
#pragma unroll
        for (int tt = 0; tt < 4; tt++) {
            const __half* s = srcs[tt] + k0;
#pragma unroll
            for (int i = 0; i < 4; i++) {
                int lin = tid + i * 256;
                int row = lin >> 3, c16 = lin & 7;
                uint32_t off = (uint32_t)(row * 128 + c16 * 16);
                cp16(sb + tt * TILEB + (off ^ ((row & 7) * 16)),
                     s + (size_t)row * F_ + c16 * 8);
            }
        }
        cpcommit();
    };

    const uint32_t xorv = (uint32_t)((t & 7) * 16);
    uint32_t aOff[4], bOff[4];
#pragma unroll
    for (int mt = 0; mt < 4; mt++) {
        int row = warpM * 64 + mt * 16 + (t & 15);
        aOff[mt] = (uint32_t)(row * 128 + (t >> 4) * 16);
    }
#pragma unroll
    for (int nt = 0; nt < 4; nt++) {
        int row = warpN * 32 + nt * 8 + (t & 7);
        bOff[nt] = (uint32_t)(row * 128 + ((t >> 3) & 1) * 16);
    }

    float acc[4][4][4];
#pragma unroll
    for (int mt = 0; mt < 4; mt++)
#pragma unroll
        for (int nt = 0; nt < 4; nt++)
#pragma unroll
            for (int j = 0; j < 4; j++) acc[mt][nt][j] = 0.f;

    loadStage(0, 0);
    loadStage(1, 1);

    for (int s = 0; s < 4; s++) {
        const int b = s & 1;
        if (s < 3) cpwait1(); else cpwait0();
        __syncthreads();
        const uint32_t sb = dynBase + b * STAGEB;
#pragma unroll
        for (int k16 = 0; k16 < 4; k16++) {
            uint32_t ah[4][4], al[4][4], bh[4][2], bl[4][2];
#pragma unroll
            for (int mt = 0; mt < 4; mt++) {
                uint32_t o = (aOff[mt] + k16 * 32) ^ xorv;
                LDSM4(ah[mt], sb + o);
                LDSM4(al[mt], sb + TILEB + o);
            }
#pragma unroll
            for (int nt = 0; nt < 4; nt++) {
                uint32_t o = (bOff[nt] + k16 * 32) ^ xorv;
                LDSM2(bh[nt], sb + 2 * TILEB + o);
                LDSM2(bl[nt], sb + 3 * TILEB + o);
            }
#pragma unroll
            for (int mt = 0; mt < 4; mt++)
#pragma unroll
                for (int nt = 0; nt < 4; nt++) {
                    MMA16816(acc[mt][nt], ah[mt], bh[nt]);
                    MMA16816(acc[mt][nt], ah[mt], bl[nt]);
                    MMA16816(acc[mt][nt], al[mt], bh[nt]);
                }
        }
        __syncthreads();
        if (s < 2) loadStage(b, s + 2);
    }

    // phase 1: exclusion + store sim + per-tile max (atomicMax on order-preserving key)
    const int qr = t >> 2, qc = (t & 3) * 2;
#pragma unroll
    for (int mt = 0; mt < 4; mt++) {
#pragma unroll
        for (int h = 0; h < 2; h++) {
            const int lr = warpM * 64 + mt * 16 + qr + h * 8;
            const int gr = rowBase + lr;
            const int qi = s_q[lr];
            float* orow = Wout + (size_t)gr * N_;
            float lm = -3.0e38f;
#pragma unroll
            for (int nt = 0; nt < 4; nt++) {
                int gc = colBase + warpN * 32 + nt * 8 + qc;
                if (gc < N_) {
                    float x = acc[mt][nt][h * 2 + 0];
                    float y = acc[mt][nt][h * 2 + 1];
                    if (gc == qi)     x = -1e9f;
                    if (gc + 1 == qi) y = -1e9f;
                    *(float2*)(orow + gc) = make_float2(x, y);
                    lm = fmaxf(lm, fmaxf(x, y));
                }
            }
            atomicMax(&s_red[lr], fkey(lm));
        }
    }
    __syncthreads();

    // phase 2: per-tile exp-sums s_t = sum fexp((x - m_t)*invT), deterministic reduction
    const float invT = g_invT[0];
#pragma unroll
    for (int mt = 0; mt < 4; mt++) {
#pragma unroll
        for (int h = 0; h < 2; h++) {
            const int lr = warpM * 64 + mt * 16 + qr + h * 8;
            const int qi = s_q[lr];
            const float mT = funkey(s_red[lr]);
            float ls = 0.f;
#pragma unroll
            for (int nt = 0; nt < 4; nt++) {
                int gc = colBase + warpN * 32 + nt * 8 + qc;
                if (gc < N_) {
                    float x = acc[mt][nt][h * 2 + 0];
                    float y = acc[mt][nt][h * 2 + 1];
                    if (gc == qi)     x = -1e9f;
                    if (gc + 1 == qi) y = -1e9f;
                    ls += fexp((x - mT) * invT) + fexp((y - mT) * invT);
                }
            }
            // quad reduce (lanes 4q..4q+3 hold same row) — fixed order
            ls += __shfl_xor_sync(0xffffffffu, ls, 1);
            ls += __shfl_xor_sync(0xffffffffu, ls, 2);
            if ((t & 3) == 0) s_red2[lr][warpN] = ls;
        }
    }
    __syncthreads();
    if (tid < BM) {
        g_pmax[(size_t)(rowBase + tid) * NT_SIM + blockIdx.x] = funkey(s_red[tid]);
        g_ptsum[(size_t)(rowBase + tid) * NT_SIM + blockIdx.x] =
            (s_red2[tid][0] + s_red2[tid][1]) + (s_red2[tid][2] + s_red2[tid][3]);
    }
}

// ========= kernel: combine per-tile stats -> row max M and 1/S =========
__global__ __launch_bounds__(256)
void rowstat_kernel()
{
    const int row = blockIdx.x;
    const int tid = threadIdx.x;
    const float invT = g_invT[0];
    __shared__ float sm[256];

    float m = -3.0e38f;
    for (int t = tid; t < NT_SIM; t += 256)
        m = fmaxf(m, g_pmax[(size_t)row * NT_SIM + t]);
    sm[tid] = m; __syncthreads();
    for (int s = 128; s > 0; s >>= 1) {
        if (tid < s) sm[tid] = fmaxf(sm[tid], sm[tid + s]);
        __syncthreads();
    }
    const float M = sm[0];
    __syncthreads();

    float s = 0.f;
    for (int t = tid; t < NT_SIM; t += 256)
        s += g_ptsum[(size_t)row * NT_SIM + t] *
             fexp((g_pmax[(size_t)row * NT_SIM + t] - M) * invT);
    sm[tid] = s; __syncthreads();
    for (int st = 128; st > 0; st >>= 1) {
        if (tid < st) sm[tid] += sm[tid + st];
        __syncthreads();
    }
    if (tid == 0) { g_rmax[row] = M; g_rinv[row] = 1.f / sm[0]; }
}

// ===== kernel: pred fused with exp — reads fp32 sim in place, writes final weights =====
// grid: (x = row block [4], y = split [98]) so same-split blocks are adjacent (aT L2 reuse)
__global__ __launch_bounds__(256, 1)
void pred_kernel(float* __restrict__ SimW)
{
    extern __shared__ __align__(16) char dsm_raw[];
    __shared__ float s_inv[BM];
    __shared__ float s_m[BM];
    char* dynPtr = (char*)(((uintptr_t)dsm_raw + 1023) & ~(uintptr_t)1023);
    const uint32_t dynBase = su(dynPtr);
    const int tid = threadIdx.x, wid = tid >> 5, t = tid & 31;
    const int warpM = wid >> 2, warpN = wid & 3;
    const int rowBase = blockIdx.x * BM;
    const int kBase = blockIdx.y * KC2;
    const int nst = (min(kBase + KC2, NPAD) - kBase) / KCH;   // 16 or 12
    const float invT = g_invT[0];

    if (tid < BM) { s_inv[tid] = g_rinv[rowBase + tid]; s_m[tid] = g_rmax[rowBase + tid]; }

    float4 pa[8];
    auto ldE = [&](int sidx) {
        const int k0 = kBase + sidx * KCH;
#pragma unroll
        for (int i = 0; i < 8; i++) {
            int lin = tid + i * 256;
            int row = lin >> 4;
            int c4 = (lin & 15) << 2;
            int gc = k0 + c4;
            pa[i] = make_float4(-1e9f, -1e9f, -1e9f, -1e9f);  // pad -> e=~0
            if (gc < N_)
                pa[i] = *(const float4*)(SimW + (size_t)(rowBase + row) * N_ + gc);
        }
    };
    // exp + weights write + fp16 split into smem (requires s_m/s_inv visible)
    auto stsE = [&](int st, int sidx) {
        const int k0 = kBase + sidx * KCH;
        char* sb = dynPtr + st * STAGEB;
#pragma unroll
        for (int i = 0; i < 8; i++) {
            int lin = tid + i * 256;
            int row = lin >> 4;
            int c4 = (lin & 15) << 2;
            int gc = k0 + c4;
            const float mM = s_m[row], inv = s_inv[row];
            float v[4] = {pa[i].x, pa[i].y, pa[i].z, pa[i].w};
            float e[4];
#pragma unroll
            for (int j = 0; j < 4; j++) e[j] = fexp((v[j] - mM) * invT);
            if (gc < N_) {
                *(float4*)(SimW + (size_t)(rowBase + row) * N_ + gc) =
                    make_float4(e[0] * inv, e[1] * inv, e[2] * inv, e[3] * inv);
            } else {
#pragma unroll
                for (int j = 0; j < 4; j++) e[j] = 0.f;
            }
            __half h[4], l[4];
#pragma unroll
            for (int j = 0; j < 4; j++) {
                h[j] = __float2half_rn(e[j]);
                l[j] = __float2half_rn(e[j] - __half2float(h[j]));
            }
            uint32_t off = (uint32_t)(row * 128 + c4 * 2) ^ (uint32_t)((row & 7) * 16);
            *(uint2*)(sb + off)         = make_uint2(pkh(h[0], h[1]), pkh(h[2], h[3]));
            *(uint2*)(sb + TILEB + off) = make_uint2(pkh(l[0], l[1]), pkh(l[2], l[3]));
        }
    };
    auto cpB = [&](int st, int sidx) {
        const int k0 = kBase + sidx * KCH;
        const uint32_t sb = dynBase + st * STAGEB;
#pragma unroll
        for (int i = 0; i < 4; i++) {
            int lin = tid + i * 256;
            int row = lin >> 3, c16 = lin & 7;
            uint32_t off = (uint32_t)(row * 128 + c16 * 16) ^ (uint32_t)((row & 7) * 16);
            cp16(sb + 2 * TILEB + off, g_aT_hi + (size_t)row * NPAD + k0 + c16 * 8);
            cp16(sb + 3 * TILEB + off, g_aT_lo + (size_t)row * NPAD + k0 + c16 * 8);
        }
        cpcommit();
    };

    const uint32_t xorv = (uint32_t)((t & 7) * 16);
    uint32_t aOff[4], bOff[4];
#pragma unroll
    for (int mt = 0; mt < 4; mt++) {
        int row = warpM * 64 + mt * 16 + (t & 15);
        aOff[mt] = (uint32_t)(row * 128 + (t >> 4) * 16);
    }
#pragma unroll
    for (int nt = 0; nt < 4; nt++) {
        int row = warpN * 32 + nt * 8 + (t & 7);
        bOff[nt] = (uint32_t)(row * 128 + ((t >> 3) & 1) * 16);
    }

    float acc[4][4][4];
#pragma unroll
    for (int mt = 0; mt < 4; mt++)
#pragma unroll
        for (int nt = 0; nt < 4; nt++)
#pragma unroll
            for (int j = 0; j < 4; j++) acc[mt][nt][j] = 0.f;

    ldE(0); cpB(0, 0);
    __syncthreads();               // s_m/s_inv visible before stsE
    stsE(0, 0); cpwait0(); __syncthreads();

    for (int s = 0; s < nst; s++) {
        const int bb = s & 1;
        if (s + 1 < nst) { ldE(s + 1); cpB(bb ^ 1, s + 1); }
        const uint32_t sb = dynBase + bb * STAGEB;
#pragma unroll
        for (int k16 = 0; k16 < 4; k16++) {
            uint32_t ah[4][4], al[4][4], bh[4][2], bl[4][2];
#pragma unroll
            for (int mt = 0; mt < 4; mt++) {
                uint32_t o = (aOff[mt] + k16 * 32) ^ xorv;
                LDSM4(ah[mt], sb + o);
                LDSM4(al[mt], sb + TILEB + o);
            }
#pragma unroll
            for (int nt = 0; nt < 4; nt++) {
                uint32_t o = (bOff[nt] + k16 * 32) ^ xorv;
                LDSM2(bh[nt], sb + 2 * TILEB + o);
                LDSM2(bl[nt], sb + 3 * TILEB + o);
            }
#pragma unroll
            for (int mt = 0; mt < 4; mt++)
#pragma unroll
                for (int nt = 0; nt < 4; nt++) {
                    MMA16816(acc[mt][nt], ah[mt], bh[nt]);
                    MMA16816(acc[mt][nt], ah[mt], bl[nt]);
                    MMA16816(acc[mt][nt], al[mt], bh[nt]);
                }
        }
        if (s + 1 < nst) { stsE(bb ^ 1, s + 1); cpwait0(); }
        __syncthreads();
    }

    // store split-K partials (unnormalized)
    float* pp = g_ppred + (size_t)blockIdx.y * (B_ * HA_);
    const int qr = t >> 2, qc = (t & 3) * 2;
#pragma unroll
    for (int mt = 0; mt < 4; mt++)
#pragma unroll
        for (int h = 0; h < 2; h++) {
            const int row = rowBase + warpM * 64 + mt * 16 + qr + h * 8;
#pragma unroll
            for (int nt = 0; nt < 4; nt++) {
                const int col = warpN * 32 + nt * 8 + qc;
                *(float2*)(pp + (size_t)row * HA_ + col) =
                    make_float2(acc[mt][nt][h * 2 + 0], acc[mt][nt][h * 2 + 1]);
            }
        }
}

// ================= kernel: split-K reduction (normalizes) =================
__global__ __launch_bounds__(256)
void predsum_kernel(float* __restrict__ outPred)
{
    const int idx = blockIdx.x * 256 + threadIdx.x;
    if (idx < B_ * HA_) {
        float s = 0.f;
        for (int t = 0; t < SPL2; t++)
            s += g_ppred[(size_t)t * (B_ * HA_) + idx];
        outPred[idx] = s * g_rinv[idx >> 7];
    }
}

// ================= launch =================
extern "C" void kernel_launch(void* const* d_in, const int* in_sizes, int n_in,
                              void* d_out, int out_size)
{
    const float*     query_obs     = (const float*)d_in[0];
    const long long* query_indices = (const long long*)d_in[1];
    const float*     W_enc         = (const float*)d_in[2];
    const float*     train_obs     = (const float*)d_in[3];
    const float*     train_actions = (const float*)d_in[4];
    const float*     logT          = (const float*)d_in[5];

    float* out_pred = (float*)d_out;
    float* out_w    = (float*)d_out + (size_t)B_ * HA_;

    __half *zth, *ztl, *zqh, *zql;
    cudaGetSymbolAddress((void**)&zth, g_zt_hi);
    cudaGetSymbolAddress((void**)&ztl, g_zt_lo);
    cudaGetSymbolAddress((void**)&zqh, g_zq_hi);
    cudaGetSymbolAddress((void**)&zql, g_zq_lo);

    cudaFuncSetAttribute(encode_kernel, cudaFuncAttributeMaxDynamicSharedMemorySize, DYNSM);
    cudaFuncSetAttribute(sim_kernel, cudaFuncAttributeMaxDynamicSharedMemorySize, DYNSM);
    cudaFuncSetAttribute(pred_kernel, cudaFuncAttributeMaxDynamicSharedMemorySize, DYNSM);

    dim3 blk(256);
    dim3 tsp(32, 8);

    prep_kernel<<<1, 1>>>(logT);
    wsplit_kernel<<<dim3(D_ / 32, F_ / 32), tsp>>>(W_enc);
    atsplit_kernel<<<dim3(NPAD / 32, HA_ / 32), tsp>>>(train_actions);
    encode_kernel<<<dim3(F_ / 128, NPAD / BM), blk, DYNSM>>>(train_obs, zth, ztl, N_);
    encode_kernel<<<dim3(F_ / 128, B_ / BM), blk, DYNSM>>>(query_obs, zqh, zql, B_);
    sim_kernel<<<dim3(NT_SIM, B_ / BM), blk, DYNSM>>>(query_indices, out_w);
    rowstat_kernel<<<B_, blk>>>();
    pred_kernel<<<dim3(B_ / BM, SPL2), blk, DYNSM>>>(out_w);
    predsum_kernel<<<(B_ * HA_ + 255) / 256, blk>>>(out_pred);
}

// round 10
// speedup vs baseline: 1.0807x; 1.0807x over previous
#include <cuda_runtime.h>
#include <cuda_fp16.h>
#include <cstdint>

// ---------------- problem constants ----------------
#define B_   512
#define N_   100000
#define NPAD 100096    // N padded to multiple of 128
#define D_   256
#define F_   256
#define HA_  128

#define BM 128

#define NT_SIM (NPAD / 128)                // 782 column tiles
#define KC2    1024                        // pred split-K chunk
#define SPL2   ((NPAD + KC2 - 1) / KC2)    // 98 splits

// mma staging geometry
#define KCH   64                           // K halves per stage (128B rows)
#define TILEB 16384                        // 128 rows * 64 halves * 2B
#define STAGEB (4 * TILEB)                 // 4 tiles per stage (encode/sim)
#define DYNSM (1024 + 2 * STAGEB)

// pred staging: 2 tiles (e_hi, aT_hi) per stage, 3 stages
#define PSTAGEB (2 * TILEB)
#define PDYNSM (1024 + 3 * PSTAGEB)

// ---------------- device scratch ----------------
__device__ __align__(16) __half g_zt_hi[(size_t)NPAD * F_];
__device__ __align__(16) __half g_zt_lo[(size_t)NPAD * F_];
__device__ __align__(16) __half g_zq_hi[(size_t)B_ * F_];
__device__ __align__(16) __half g_zq_lo[(size_t)B_ * F_];
__device__ __align__(16) __half g_wt_hi[(size_t)F_ * D_];   // W^T split
__device__ __align__(16) __half g_wt_lo[(size_t)F_ * D_];
__device__ __align__(16) __half g_e_hi[(size_t)B_ * NPAD];  // exp(e) fp16 (pad zeroed)
__device__ __align__(16) __half g_aT_hi[(size_t)HA_ * NPAD];// actions^T fp16
__device__ float  g_pmax[(size_t)B_ * NT_SIM];   // per (row, tile) max
__device__ float  g_ptsum[(size_t)B_ * NT_SIM];  // per (row, tile) exp-sum (tile-shifted)
__device__ float  g_rmax[B_];
__device__ float  g_rinv[B_];
__device__ float  g_invT[1];
__device__ float  g_ppred[(size_t)SPL2 * B_ * HA_];

// ---------------- helpers ----------------
__device__ __forceinline__ unsigned su(const void* p) {
    return (unsigned)__cvta_generic_to_shared(p);
}
__device__ __forceinline__ void cp16(unsigned d, const void* s) {
    asm volatile("cp.async.cg.shared.global [%0], [%1], 16;" :: "r"(d), "l"(s));
}
__device__ __forceinline__ void cpcommit() { asm volatile("cp.async.commit_group;"); }
__device__ __forceinline__ void cpwait0()  { asm volatile("cp.async.wait_group 0;"); }
__device__ __forceinline__ void cpwait1()  { asm volatile("cp.async.wait_group 1;"); }
__device__ __forceinline__ void cpwait2()  { asm volatile("cp.async.wait_group 2;"); }

#define LDSM4(r, addr) \
    asm volatile("ldmatrix.sync.aligned.m8n8.x4.shared.b16 {%0,%1,%2,%3}, [%4];" \
        : "=r"((r)[0]), "=r"((r)[1]), "=r"((r)[2]), "=r"((r)[3]) : "r"(addr))
#define LDSM2(r, addr) \
    asm volatile("ldmatrix.sync.aligned.m8n8.x2.shared.b16 {%0,%1}, [%2];" \
        : "=r"((r)[0]), "=r"((r)[1]) : "r"(addr))
#define MMA16816(d, a, b) \
    asm volatile("mma.sync.aligned.m16n8k16.row.col.f32.f16.f16.f32 " \
        "{%0,%1,%2,%3}, {%4,%5,%6,%7}, {%8,%9}, {%0,%1,%2,%3};" \
        : "+f"((d)[0]), "+f"((d)[1]), "+f"((d)[2]), "+f"((d)[3]) \
        : "r"((a)[0]), "r"((a)[1]), "r"((a)[2]), "r"((a)[3]), "r"((b)[0]), "r"((b)[1]))

__device__ __forceinline__ unsigned fkey(float f) {
    unsigned u = __float_as_uint(f);
    return (u & 0x80000000u) ? ~u : (u | 0x80000000u);
}
__device__ __forceinline__ float funkey(unsigned k) {
    return __uint_as_float((k & 0x80000000u) ? (k & 0x7FFFFFFFu) : ~k);
}
__device__ __forceinline__ uint32_t pkh(__half a, __half b) {
    __half2 h = __halves2half2(a, b);
    return *(uint32_t*)&h;
}

__device__ __forceinline__ float fexp(float x)
{
    x = fmaxf(x, -87.0f);
    float t = x * 1.4426950408889634f;
    float n = rintf(t);
    float f = t - n;
    float p =            1.5403530393e-4f;
    p = fmaf(p, f, 1.3333558146e-3f);
    p = fmaf(p, f, 9.6181291076e-3f);
    p = fmaf(p, f, 5.5504108664e-2f);
    p = fmaf(p, f, 2.4022650696e-1f);
    p = fmaf(p, f, 6.9314718056e-1f);
    p = fmaf(p, f, 1.0f);
    int ni = (int)n;
    float s = __int_as_float((ni + 127) << 23);
    return p * s;
}

// ================= kernel: prep (invT) =================
__global__ void prep_kernel(const float* __restrict__ logT)
{
    g_invT[0] = expf(-logT[0]);
}

// ================= kernel: W_enc transpose + fp16 split =================
__global__ void wsplit_kernel(const float* __restrict__ W)
{
    __shared__ float s[32][33];
    const int k0 = blockIdx.x * 32, f0 = blockIdx.y * 32;
    const int tx = threadIdx.x, ty = threadIdx.y;
#pragma unroll
    for (int l = 0; l < 4; l++)
        s[ty + l * 8][tx] = W[(size_t)(k0 + ty + l * 8) * F_ + f0 + tx];
    __syncthreads();
#pragma unroll
    for (int l = 0; l < 4; l++) {
        float v = s[tx][ty + l * 8];
        __half h = __float2half_rn(v);
        __half lo = __float2half_rn(v - __half2float(h));
        g_wt_hi[(size_t)(f0 + ty + l * 8) * D_ + k0 + tx] = h;
        g_wt_lo[(size_t)(f0 + ty + l * 8) * D_ + k0 + tx] = lo;
    }
}

// ================= kernel: actions transpose -> fp16 hi =================
__global__ void atsplit_kernel(const float* __restrict__ Act)
{
    __shared__ float s[32][33];
    const int n0 = blockIdx.x * 32, j0 = blockIdx.y * 32;
    const int tx = threadIdx.x, ty = threadIdx.y;
#pragma unroll
    for (int l = 0; l < 4; l++) {
        int n = n0 + ty + l * 8;
        float v = 0.f;
        if (n < N_) v = Act[(size_t)n * HA_ + j0 + tx];
        s[ty + l * 8][tx] = v;
    }
    __syncthreads();
#pragma unroll
    for (int l = 0; l < 4; l++) {
        int j = j0 + ty + l * 8;
        g_aT_hi[(size_t)j * NPAD + n0 + tx] = __float2half_rn(s[tx][ty + l * 8]);
    }
}

// ================= kernel: encode via mma.sync (fp16-split, 3 products) =================
__global__ __launch_bounds__(256, 1)
void encode_kernel(const float* __restrict__ A,
                   __half* __restrict__ Zh, __half* __restrict__ Zl, int M)
{
    extern __shared__ __align__(16) char dsm_raw[];
    char* dynPtr = (char*)(((uintptr_t)dsm_raw + 1023) & ~(uintptr_t)1023);
    const uint32_t dynBase = su(dynPtr);
    const int tid = threadIdx.x, wid = tid >> 5, t = tid & 31;
    const int warpM = wid >> 2, warpN = wid & 3;
    const int rowBase = blockIdx.y * BM;
    const int colBase = blockIdx.x * 128;

    float4 pa[8];
    auto ldA = [&](int k0) {
#pragma unroll
        for (int i = 0; i < 8; i++) {
            int lin = tid + i * 256;
            int row = lin >> 4;
            int c4 = (lin & 15) << 2;
            int gr = rowBase + row;
            pa[i] = make_float4(0.f, 0.f, 0.f, 0.f);
            if (gr < M) pa[i] = *(const float4*)(A + (size_t)gr * D_ + k0 + c4);
        }
    };
    auto stsA = [&](int st) {
        char* sb = dynPtr + st * STAGEB;
#pragma unroll
        for (int i = 0; i < 8; i++) {
            int lin = tid + i * 256;
            int row = lin >> 4;
            int c4 = (lin & 15) << 2;
            uint32_t off = (uint32_t)(row * 128 + c4 * 2) ^ (uint32_t)((row & 7) * 16);
            float v[4] = {pa[i].x, pa[i].y, pa[i].z, pa[i].w};
            __half h[4], l[4];
#pragma unroll
            for (int j = 0; j < 4; j++) {
                h[j] = __float2half_rn(v[j]);
                l[j] = __float2half_rn(v[j] - __half2float(h[j]));
            }
            *(uint2*)(sb + off)         = make_uint2(pkh(h[0], h[1]), pkh(h[2], h[3]));
            *(uint2*)(sb + TILEB + off) = make_uint2(pkh(l[0], l[1]), pkh(l[2], l[3]));
        }
    };
    auto cpB = [&](int st, int k0) {
        const uint32_t sb = dynBase + st * STAGEB;
#pragma unroll
        for (int i = 0; i < 4; i++) {
            int lin = tid + i * 256;
            int row = lin >> 3, c16 = lin & 7;
            uint32_t off = (uint32_t)(row * 128 + c16 * 16) ^ (uint32_t)((row & 7) * 16);
            cp16(sb + 2 * TILEB + off, g_wt_hi + (size_t)(colBase + row) * D_ + k0 + c16 * 8);
            cp16(sb + 3 * TILEB + off, g_wt_lo + (size_t)(colBase + row) * D_ + k0 + c16 * 8);
        }
        cpcommit();
    };

    const uint32_t xorv = (uint32_t)((t & 7) * 16);
    uint32_t aOff[4], bOff[4];
#pragma unroll
    for (int mt = 0; mt < 4; mt++) {
        int row = warpM * 64 + mt * 16 + (t & 15);
        aOff[mt] = (uint32_t)(row * 128 + (t >> 4) * 16);
    }
#pragma unroll
    for (int nt = 0; nt < 4; nt++) {
        int row = warpN * 32 + nt * 8 + (t & 7);
        bOff[nt] = (uint32_t)(row * 128 + ((t >> 3) & 1) * 16);
    }

    float acc[4][4][4];
#pragma unroll
    for (int mt = 0; mt < 4; mt++)
#pragma unroll
        for (int nt = 0; nt < 4; nt++)
#pragma unroll
            for (int j = 0; j < 4; j++) acc[mt][nt][j] = 0.f;

    ldA(0); cpB(0, 0);
    stsA(0); cpwait0(); __syncthreads();

    for (int it = 0; it < 4; it++) {
        const int cur = it & 1;
        if (it < 3) { ldA((it + 1) * KCH); cpB(cur ^ 1, (it + 1) * KCH); }
        const uint32_t sb = dynBase + cur * STAGEB;
#pragma unroll
        for (int k16 = 0; k16 < 4; k16++) {
            uint32_t ah[4][4], al[4][4], bh[4][2], bl[4][2];
#pragma unroll
            for (int mt = 0; mt < 4; mt++) {
                uint32_t o = (aOff[mt] + k16 * 32) ^ xorv;
                LDSM4(ah[mt], sb + o);
                LDSM4(al[mt], sb + TILEB + o);
            }
#pragma unroll
            for (int nt = 0; nt < 4; nt++) {
                uint32_t o = (bOff[nt] + k16 * 32) ^ xorv;
                LDSM2(bh[nt], sb + 2 * TILEB + o);
                LDSM2(bl[nt], sb + 3 * TILEB + o);
            }
#pragma unroll
            for (int mt = 0; mt < 4; mt++)
#pragma unroll
                for (int nt = 0; nt < 4; nt++) {
                    MMA16816(acc[mt][nt], ah[mt], bh[nt]);
                    MMA16816(acc[mt][nt], ah[mt], bl[nt]);
                    MMA16816(acc[mt][nt], al[mt], bh[nt]);
                }
        }
        if (it < 3) { stsA(cur ^ 1); cpwait0(); }
        __syncthreads();
    }

    const int qr = t >> 2, qc = (t & 3) * 2;
#pragma unroll
    for (int mt = 0; mt < 4; mt++)
#pragma unroll
        for (int h = 0; h < 2; h++) {
            const size_t m = (size_t)(rowBase + warpM * 64 + mt * 16 + qr + h * 8);
#pragma unroll
            for (int nt = 0; nt < 4; nt++) {
                const int gc = colBase + warpN * 32 + nt * 8 + qc;
                float x = acc[mt][nt][h * 2 + 0];
                float y = acc[mt][nt][h * 2 + 1];
                __half hx = __float2half_rn(x), hy = __float2half_rn(y);
                __half lx = __float2half_rn(x - __half2float(hx));
                __half ly = __float2half_rn(y - __half2float(hy));
                *(__half2*)(Zh + m * F_ + gc) = __halves2half2(hx, hy);
                *(__half2*)(Zl + m * F_ + gc) = __halves2half2(lx, ly);
            }
        }
}

// ================= kernel: sim via mma.sync + per-tile (max, exp-sum) =================
__global__ __launch_bounds__(256, 1)
void sim_kernel(const long long* __restrict__ qidx, float* __restrict__ Wout)
{
    extern __shared__ __align__(16) char dsm_raw[];
    __shared__ int      s_q[BM];
    __shared__ unsigned s_red[BM];
    __shared__ float    s_red2[BM][4];

    char* dynPtr = (char*)(((uintptr_t)dsm_raw + 1023) & ~(uintptr_t)1023);
    const uint32_t dynBase = su(dynPtr);
    const int tid = threadIdx.x, wid = tid >> 5, t = tid & 31;
    const int warpM = wid >> 2, warpN = wid & 3;
    const int rowBase = blockIdx.y * BM;
    const int colBase = blockIdx.x * 128;

    if (tid < BM) { s_q[tid] = (int)qidx[rowBase + tid]; s_red[tid] = 0u; }

    const __half* srcs[4] = { g_zq_hi + (size_t)rowBase * F_, g_zq_lo + (size_t)rowBase * F_,
                              g_zt_hi + (size_t)colBase * F_, g_zt_lo + (size_t)colBase * F_ };
    auto loadStage = [&](int st, int ck) {
        const int k0 = ck * KCH;
        const uint32_t sb = dynBase + st * STAGEB;
#pragma unroll
        for (int tt = 0; tt < 4; tt++) {
            const __half* s = srcs[tt] + k0;
#pragma unroll
            for (int i = 0; i < 4; i++) {
                int lin = tid + i * 256;
                int row = lin >> 3, c16 = lin & 7;
                uint32_t off = (uint32_t)(row * 128 + c16 * 16);
                cp16(sb + tt * TILEB + (off ^ ((row & 7) * 16)),
                     s + (size_t)row * F_ + c16 * 8);
            }
        }
        cpcommit();
    };

    const uint32_t xorv = (uint32_t)((t & 7) * 16);
    uint32_t aOff[4], bOff[4];
#pragma unroll
    for (int mt = 0; mt < 4; mt++) {
        int row = warpM * 64 + mt * 16 + (t & 15);
        aOff[mt] = (uint32_t)(row * 128 + (t >> 4) * 16);
    }
#pragma unroll
    for (int nt = 0; nt < 4; nt++) {
        int row = warpN * 32 + nt * 8 + (t & 7);
        bOff[nt] = (uint32_t)(row * 128 + ((t >> 3) & 1) * 16);
    }

    float acc[4][4][4];
#pragma unroll
    for (int mt = 0; mt < 4; mt++)
#pragma unroll
        for (int nt = 0; nt < 4; nt++)
#pragma unroll
            for (int j = 0; j < 4; j++) acc[mt][nt][j] = 0.f;

    loadStage(0, 0);
    loadStage(1, 1);

    for (int s = 0; s < 4; s++) {
        const int b = s & 1;
        if (s < 3) cpwait1(); else cpwait0();
        __syncthreads();
        const uint32_t sb = dynBase + b * STAGEB;
#pragma unroll
        for (int k16 = 0; k16 < 4; k16++) {
            uint32_t ah[4][4], al[4][4], bh[4][2], bl[4][2];
#pragma unroll
            for (int mt = 0; mt < 4; mt++) {
                uint32_t o = (aOff[mt] + k16 * 32) ^ xorv;
                LDSM4(ah[mt], sb + o);
                LDSM4(al[mt], sb + TILEB + o);
            }
#pragma unroll
            for (int nt = 0; nt < 4; nt++) {
                uint32_t o = (bOff[nt] + k16 * 32) ^ xorv;
                LDSM2(bh[nt], sb + 2 * TILEB + o);
                LDSM2(bl[nt], sb + 3 * TILEB + o);
            }
#pragma unroll
            for (int mt = 0; mt < 4; mt++)
#pragma unroll
                for (int nt = 0; nt < 4; nt++) {
                    MMA16816(acc[mt][nt], ah[mt], bh[nt]);
                    MMA16816(acc[mt][nt], ah[mt], bl[nt]);
                    MMA16816(acc[mt][nt], al[mt], bh[nt]);
                }
        }
        __syncthreads();
        if (s < 2) loadStage(b, s + 2);
    }

    // phase 1: exclusion + store sim + per-tile max
    const int qr = t >> 2, qc = (t & 3) * 2;
#pragma unroll
    for (int mt = 0; mt < 4; mt++) {
#pragma unroll
        for (int h = 0; h < 2; h++) {
            const int lr = warpM * 64 + mt * 16 + qr + h * 8;
            const int gr = rowBase + lr;
            const int qi = s_q[lr];
            float* orow = Wout + (size_t)gr * N_;
            float lm = -3.0e38f;
#pragma unroll
            for (int nt = 0; nt < 4; nt++) {
                int gc = colBase + warpN * 32 + nt * 8 + qc;
                if (gc < N_) {
                    float x = acc[mt][nt][h * 2 + 0];
                    float y = acc[mt][nt][h * 2 + 1];
                    if (gc == qi)     x = -1e9f;
                    if (gc + 1 == qi) y = -1e9f;
                    *(float2*)(orow + gc) = make_float2(x, y);
                    lm = fmaxf(lm, fmaxf(x, y));
                }
            }
            atomicMax(&s_red[lr], fkey(lm));
        }
    }
    __syncthreads();

    // phase 2: per-tile exp-sums, deterministic fixed-order reduction
    const float invT = g_invT[0];
#pragma unroll
    for (int mt = 0; mt < 4; mt++) {
#pragma unroll
        for (int h = 0; h < 2; h++) {
            const int lr = warpM * 64 + mt * 16 + qr + h * 8;
            const int qi = s_q[lr];
            const float mT = funkey(s_red[lr]);
            float ls = 0.f;
#pragma unroll
            for (int nt = 0; nt < 4; nt++) {
                int gc = colBase + warpN * 32 + nt * 8 + qc;
                if (gc < N_) {
                    float x = acc[mt][nt][h * 2 + 0];
                    float y = acc[mt][nt][h * 2 + 1];
                    if (gc == qi)     x = -1e9f;
                    if (gc + 1 == qi) y = -1e9f;
                    ls += fexp((x - mT) * invT) + fexp((y - mT) * invT);
                }
            }
            ls += __shfl_xor_sync(0xffffffffu, ls, 1);
            ls += __shfl_xor_sync(0xffffffffu, ls, 2);
            if ((t & 3) == 0) s_red2[lr][warpN] = ls;
        }
    }
    __syncthreads();
    if (tid < BM) {
        g_pmax[(size_t)(rowBase + tid) * NT_SIM + blockIdx.x] = funkey(s_red[tid]);
        g_ptsum[(size_t)(rowBase + tid) * NT_SIM + blockIdx.x] =
            (s_red2[tid][0] + s_red2[tid][1]) + (s_red2[tid][2] + s_red2[tid][3]);
    }
}

// ========= kernel: combine per-tile stats -> row max M and 1/S =========
__global__ __launch_bounds__(256)
void rowstat_kernel()
{
    const int row = blockIdx.x;
    const int tid = threadIdx.x;
    const float invT = g_invT[0];
    __shared__ float sm[256];

    float m = -3.0e38f;
    for (int t = tid; t < NT_SIM; t += 256)
        m = fmaxf(m, g_pmax[(size_t)row * NT_SIM + t]);
    sm[tid] = m; __syncthreads();
    for (int s = 128; s > 0; s >>= 1) {
        if (tid < s) sm[tid] = fmaxf(sm[tid], sm[tid + s]);
        __syncthreads();
    }
    const float M = sm[0];
    __syncthreads();

    float s = 0.f;
    for (int t = tid; t < NT_SIM; t += 256)
        s += g_ptsum[(size_t)row * NT_SIM + t] *
             fexp((g_pmax[(size_t)row * NT_SIM + t] - M) * invT);
    sm[tid] = s; __syncthreads();
    for (int st = 128; st > 0; st >>= 1) {
        if (tid < st) sm[tid] += sm[tid + st];
        __syncthreads();
    }
    if (tid == 0) { g_rmax[row] = M; g_rinv[row] = 1.f / sm[0]; }
}

// ===== kernel: finalize — w = e*inv (fp32, in place) + e_hi fp16 plane =====
__global__ __launch_bounds__(256)
void finalize_kernel(float* __restrict__ SimW)
{
    const int row = blockIdx.y;
    const int tid = threadIdx.x;
    const float invT = g_invT[0];
    const float m = g_rmax[row];
    const float inv = g_rinv[row];
    const int i4 = blockIdx.x * 256 + tid;
    if (i4 < NPAD / 4) {
        const int gc = i4 * 4;
        uint2 uh = make_uint2(0u, 0u);
        if (gc < N_) {
            float4 v = *(const float4*)(SimW + (size_t)row * N_ + gc);
            float e0 = fexp((v.x - m) * invT);
            float e1 = fexp((v.y - m) * invT);
            float e2 = fexp((v.z - m) * invT);
            float e3 = fexp((v.w - m) * invT);
            *(float4*)(SimW + (size_t)row * N_ + gc) =
                make_float4(e0 * inv, e1 * inv, e2 * inv, e3 * inv);
            uh = make_uint2(pkh(__float2half_rn(e0), __float2half_rn(e1)),
                            pkh(__float2half_rn(e2), __float2half_rn(e3)));
        }
        *(uint2*)(g_e_hi + (size_t)row * NPAD + gc) = uh;
    }
}

// ===== kernel: pred — single-product HMMA (e_hi x aT_hi), 3-stage pipeline =====
// grid: (x = row block [4], y = split [98]); adjacent blocks share aT chunk (L2)
__global__ __launch_bounds__(256, 1)
void pred_kernel()
{
    extern __shared__ __align__(16) char dsm_raw[];
    char* dynPtr = (char*)(((uintptr_t)dsm_raw + 1023) & ~(uintptr_t)1023);
    const uint32_t dynBase = su(dynPtr);
    const int tid = threadIdx.x, wid = tid >> 5, t = tid & 31;
    const int warpM = wid >> 2, warpN = wid & 3;
    const int rowBase = blockIdx.x * BM;
    const int kBase = blockIdx.y * KC2;
    const int nst = (min(kBase + KC2, NPAD) - kBase) / KCH;   // 16 or 12

    auto loadStage = [&](int st, int sidx) {
        const int k0 = kBase + sidx * KCH;
        const uint32_t sb = dynBase + st * PSTAGEB;
#pragma unroll
        for (int i = 0; i < 4; i++) {
            int lin = tid + i * 256;
            int row = lin >> 3, c16 = lin & 7;
            uint32_t off = (uint32_t)(row * 128 + c16 * 16) ^ (uint32_t)((row & 7) * 16);
            cp16(sb + off,         g_e_hi  + (size_t)(rowBase + row) * NPAD + k0 + c16 * 8);
            cp16(sb + TILEB + off, g_aT_hi + (size_t)row * NPAD + k0 + c16 * 8);
        }
        cpcommit();
    };

    const uint32_t xorv = (uint32_t)((t & 7) * 16);
    uint32_t aOff[4], bOff[4];
#pragma unroll
    for (int mt = 0; mt < 4; mt++) {
        int row = warpM * 64 + mt * 16 + (t & 15);
        aOff[mt] = (uint32_t)(row * 128 + (t >> 4) * 16);
    }
#pragma unroll
    for (int nt = 0; nt < 4; nt++) {
        int row = warpN * 32 + nt * 8 + (t & 7);
        bOff[nt] = (uint32_t)(row * 128 + ((t >> 3) & 1) * 16);
    }

    float acc[4][4][4];
#pragma unroll
    for (int mt = 0; mt < 4; mt++)
#pragma unroll
        for (int nt = 0; nt < 4; nt++)
#pragma unroll
            for (int j = 0; j < 4; j++) acc[mt][nt][j] = 0.f;

    loadStage(0, 0);
    loadStage(1, 1);
    loadStage(2, 2);   // nst >= 12 always

    for (int s = 0; s < nst; s++) {
        const int bb = s % 3;
        const int rem = nst - s - 1;           // stages still to consume after s
        if (rem >= 2) cpwait2(); else if (rem == 1) cpwait1(); else cpwait0();
        __syncthreads();
        const uint32_t sb = dynBase + bb * PSTAGEB;
#pragma unroll
        for (int k16 = 0; k16 < 4; k16++) {
            uint32_t eh[4][4], at[4][2];
#pragma unroll
            for (int mt = 0; mt < 4; mt++)
                LDSM4(eh[mt], sb + ((aOff[mt] + k16 * 32) ^ xorv));
#pragma unroll
            for (int nt = 0; nt < 4; nt++)
                LDSM2(at[nt], sb + TILEB + ((bOff[nt] + k16 * 32) ^ xorv));
#pragma unroll
            for (int mt = 0; mt < 4; mt++)
#pragma unroll
                for (int nt = 0; nt < 4; nt++)
                    MMA16816(acc[mt][nt], eh[mt], at[nt]);
        }
        __syncthreads();
        if (s + 3 < nst) loadStage(bb, s + 3);
    }

    // store split-K partials (unnormalized)
    float* pp = g_ppred + (size_t)blockIdx.y * (B_ * HA_);
    const int qr = t >> 2, qc = (t & 3) * 2;
#pragma unroll
    for (int mt = 0; mt < 4; mt++)
#pragma unroll
        for (int h = 0; h < 2; h++) {
            const int row = rowBase + warpM * 64 + mt * 16 + qr + h * 8;
#pragma unroll
            for (int nt = 0; nt < 4; nt++) {
                const int col = warpN * 32 + nt * 8 + qc;
                *(float2*)(pp + (size_t)row * HA_ + col) =
                    make_float2(acc[mt][nt][h * 2 + 0], acc[mt][nt][h * 2 + 1]);
            }
        }
}

// ================= kernel: split-K reduction (normalizes) =================
__global__ __launch_bounds__(256)
void predsum_kernel(float* __restrict__ outPred)
{
    const int idx = blockIdx.x * 256 + threadIdx.x;
    if (idx < B_ * HA_) {
        float s = 0.f;
        for (int t = 0; t < SPL2; t++)
            s += g_ppred[(size_t)t * (B_ * HA_) + idx];
        outPred[idx] = s * g_rinv[idx >> 7];
    }
}

// ================= launch =================
extern "C" void kernel_launch(void* const* d_in, const int* in_sizes, int n_in,
                              void* d_out, int out_size)
{
    const float*     query_obs     = (const float*)d_in[0];
    const long long* query_indices = (const long long*)d_in[1];
    const float*     W_enc         = (const float*)d_in[2];
    const float*     train_obs     = (const float*)d_in[3];
    const float*     train_actions = (const float*)d_in[4];
    const float*     logT          = (const float*)d_in[5];

    float* out_pred = (float*)d_out;
    float* out_w    = (float*)d_out + (size_t)B_ * HA_;

    __half *zth, *ztl, *zqh, *zql;
    cudaGetSymbolAddress((void**)&zth, g_zt_hi);
    cudaGetSymbolAddress((void**)&ztl, g_zt_lo);
    cudaGetSymbolAddress((void**)&zqh, g_zq_hi);
    cudaGetSymbolAddress((void**)&zql, g_zq_lo);

    cudaFuncSetAttribute(encode_kernel, cudaFuncAttributeMaxDynamicSharedMemorySize, DYNSM);
    cudaFuncSetAttribute(sim_kernel, cudaFuncAttributeMaxDynamicSharedMemorySize, DYNSM);
    cudaFuncSetAttribute(pred_kernel, cudaFuncAttributeMaxDynamicSharedMemorySize, PDYNSM);

    dim3 blk(256);
    dim3 tsp(32, 8);

    prep_kernel<<<1, 1>>>(logT);
    wsplit_kernel<<<dim3(D_ / 32, F_ / 32), tsp>>>(W_enc);
    atsplit_kernel<<<dim3(NPAD / 32, HA_ / 32), tsp>>>(train_actions);
    encode_kernel<<<dim3(F_ / 128, NPAD / BM), blk, DYNSM>>>(train_obs, zth, ztl, N_);
    encode_kernel<<<dim3(F_ / 128, B_ / BM), blk, DYNSM>>>(query_obs, zqh, zql, B_);
    sim_kernel<<<dim3(NT_SIM, B_ / BM), blk, DYNSM>>>(query_indices, out_w);
    rowstat_kernel<<<B_, blk>>>();
    finalize_kernel<<<dim3((NPAD / 4 + 255) / 256, B_), blk>>>(out_w);
    pred_kernel<<<dim3(B_ / BM, SPL2), blk, PDYNSM>>>();
    predsum_kernel<<<(B_ * HA_ + 255) / 256, blk>>>(out_pred);
}